// round 7
// baseline (speedup 1.0000x reference)
#include <cuda_runtime.h>
#include <cuda_bf16.h>

// STN_fixTheta: fused 8x nearest-upsample + dual bilinear grid_sample.
// gt: [8,1,128,256] f32, theta: [8,6] f32.
// out: box [8,1,1024,2048] f32 followed by boxy [8,1,1024,2048] f32.
//
// 2D warp tiling (warp = 4 rows x 8 lanes x 8 px) keeps each warp-gather to
// ~2-4 gt cache lines. __launch_bounds__(256,4) unlocks 64 regs so all 32
// bilinear taps of a thread's 8 pixels are in flight simultaneously.
// theta loaded as 3x float2 (b*6 floats is always 8-byte aligned).

namespace {
constexpr int NB  = 8;
constexpr int HIN = 128;
constexpr int WIN = 256;
constexpr int HO  = 1024;
constexpr int WO  = 2048;
constexpr int PX  = 8;     // pixels per thread (8-aligned group)

// floor via 2^23 bias: no F2I/I2F cvt-pipe ops. Valid for |x| < ~4e6.
__device__ __forceinline__ void ffloor(float x, float& f, int& i) {
    const float MAGIC = 12582912.0f;            // 1.5 * 2^23
    float tt = x + MAGIC;                       // RNE to integer
    float r  = tt - MAGIC;
    int   ri = __float_as_int(tt) - 0x4B400000; // integer bits
    if (r > x) { r -= 1.0f; ri -= 1; }          // round -> floor correction
    f = r; i = ri;
}

__global__ __launch_bounds__(256, 4) void stn_kernel(
    const float* __restrict__ gt,
    const float* __restrict__ theta,
    float* __restrict__ out)
{
    const int tid  = threadIdx.x;
    const int w    = tid >> 5;           // warp 0..7
    const int lane = tid & 31;
    const int lx   = lane & 7;           // 8 lanes in x
    const int ly   = lane >> 3;          // 4 rows in y
    const int wx   = w & 1;              // 2 warps in x
    const int wy   = w >> 1;             // 4 warps in y

    // block tile: 128 px wide x 16 rows
    const int xo0 = blockIdx.x * 128 + wx * 64 + lx * 8;
    const int yo  = blockIdx.y * 16  + wy * 4  + ly;
    const int b   = blockIdx.z;

    const float2 th01 = __ldg(reinterpret_cast<const float2*>(theta + b * 6 + 0));
    const float2 th23 = __ldg(reinterpret_cast<const float2*>(theta + b * 6 + 2));
    const float2 th45 = __ldg(reinterpret_cast<const float2*>(theta + b * 6 + 4));
    const float t0 = th01.x, t1 = th01.y, t2 = th23.x, t3 = th23.y;
    const float t4 = th45.x, t5 = th45.y;

    const float ys = (yo + 0.5f) * (2.0f / HO) - 1.0f;
    const float* __restrict__ g = gt + b * (HIN * WIN);

    // ---------------- boxy: one value per thread ----------------
    const float gyy  = fmaf(t4, ys, t5);
    const float iyy  = (fmaf(gyy, (float)HO, (float)HO) - 1.0f) * 0.5f;
    float iy0f; int iy0y;
    ffloor(iyy, iy0f, iy0y);
    const float wyy  = iyy - iy0f;
    const bool  ok0  = (unsigned)iy0y < (unsigned)HO;
    const bool  ok1  = (unsigned)(iy0y + 1) < (unsigned)HO;
    float vy = 0.0f;
    if (ok0 | ok1) {
        const int   xc  = xo0 >> 3;      // gt column (constant over 8 px)
        const int   ry0 = (min(max(iy0y, 0), HO - 1)) >> 3;
        const int   ry1 = (min(max(iy0y + 1, 0), HO - 1)) >> 3;
        const float wA  = ok0 ? (1.0f - wyy) : 0.0f;
        const float wB  = ok1 ? wyy : 0.0f;
        vy = wA * g[ry0 * WIN + xc] + wB * g[ry1 * WIN + xc];
    }

    // ---------------- box: segment classification ----------------
    const float xs0 = (xo0 + 0.5f) * (2.0f / WO) - 1.0f;
    const float gx0 = fmaf(t0, xs0, fmaf(t1, ys, t2));
    const float gy0 = fmaf(t3, xs0, fmaf(t4, ys, t5));
    const float ixb = (fmaf(gx0, (float)WO, (float)WO) - 1.0f) * 0.5f;
    const float iyb = (fmaf(gy0, (float)HO, (float)HO) - 1.0f) * 0.5f;
    const float sx  = t0;           // d ix / d xo
    const float sy  = t3 * 0.5f;    // d iy / d xo

    const float ix7 = fmaf(7.0f, sx, ixb);
    const float iy7 = fmaf(7.0f, sy, iyb);
    const float ixmin = fminf(ixb, ix7), ixmax = fmaxf(ixb, ix7);
    const float iymin = fminf(iyb, iy7), iymax = fmaxf(iyb, iy7);

    float v[PX];

    if (ixmax < -1.0f || ixmin >= (float)WO || iymax < -1.0f || iymin >= (float)HO) {
        #pragma unroll
        for (int j = 0; j < PX; ++j) v[j] = 0.0f;
    } else if (ixmin >= 0.0f && ixmax < (float)(WO - 1) &&
               iymin >= 0.0f && iymax < (float)(HO - 1)) {
        // fully interior: full 8-px batch — 32 independent loads in flight
        int   o00[PX], o10[PX], o01[PX], o11[PX];
        float fwx[PX], fwy[PX];
        #pragma unroll
        for (int j = 0; j < PX; ++j) {
            const float ix = fmaf((float)j, sx, ixb);
            const float iy = fmaf((float)j, sy, iyb);
            float fx, fy; int ix0, iy0;
            ffloor(ix, fx, ix0);
            ffloor(iy, fy, iy0);
            fwx[j] = ix - fx;
            fwy[j] = iy - fy;
            const int x0 = ix0 >> 3;
            const int x1 = (ix0 + 1) >> 3;
            const int y0 = iy0 >> 3;
            const int y1 = (iy0 + 1) >> 3;
            o00[j] = (y0 << 8) + x0;
            o10[j] = (y0 << 8) + x1;
            o01[j] = (y1 << 8) + x0;
            o11[j] = (y1 << 8) + x1;
        }
        float l00[PX], l10[PX], l01[PX], l11[PX];
        #pragma unroll
        for (int j = 0; j < PX; ++j) {
            l00[j] = g[o00[j]];
            l10[j] = g[o10[j]];
            l01[j] = g[o01[j]];
            l11[j] = g[o11[j]];
        }
        #pragma unroll
        for (int j = 0; j < PX; ++j) {
            const float a  = fmaf(fwx[j], l10[j] - l00[j], l00[j]);
            const float cc = fmaf(fwx[j], l11[j] - l01[j], l01[j]);
            v[j] = fmaf(fwy[j], cc - a, a);
        }
    } else {
        // edge/mixed group: general predicated path (rare)
        #pragma unroll
        for (int j = 0; j < PX; ++j) {
            const float ix = fmaf((float)j, sx, ixb);
            const float iy = fmaf((float)j, sy, iyb);
            float fx, fy; int ix0, iy0;
            ffloor(ix, fx, ix0);
            ffloor(iy, fy, iy0);
            const float wx_ = ix - fx;
            const float wy_ = iy - fy;
            const bool xv0 = (unsigned)ix0       < (unsigned)WO;
            const bool xv1 = (unsigned)(ix0 + 1) < (unsigned)WO;
            const bool yv0 = (unsigned)iy0       < (unsigned)HO;
            const bool yv1 = (unsigned)(iy0 + 1) < (unsigned)HO;
            const int x0 = (min(max(ix0, 0), WO - 1)) >> 3;
            const int x1 = (min(max(ix0 + 1, 0), WO - 1)) >> 3;
            const int y0 = (min(max(iy0, 0), HO - 1)) >> 3;
            const int y1 = (min(max(iy0 + 1, 0), HO - 1)) >> 3;
            const float w00 = (xv0 && yv0) ? (1.0f - wx_) * (1.0f - wy_) : 0.0f;
            const float w10 = (xv1 && yv0) ? wx_ * (1.0f - wy_) : 0.0f;
            const float w01 = (xv0 && yv1) ? (1.0f - wx_) * wy_ : 0.0f;
            const float w11 = (xv1 && yv1) ? wx_ * wy_ : 0.0f;
            v[j] = w00 * g[(y0 << 8) + x0]
                 + w10 * g[(y0 << 8) + x1]
                 + w01 * g[(y1 << 8) + x0]
                 + w11 * g[(y1 << 8) + x1];
        }
    }

    const long long pix = ((long long)b * HO + yo) * WO + xo0;
    float4* ob = reinterpret_cast<float4*>(out + pix);
    ob[0] = make_float4(v[0], v[1], v[2], v[3]);
    ob[1] = make_float4(v[4], v[5], v[6], v[7]);
    float4* oy = reinterpret_cast<float4*>(out + (long long)NB * HO * WO + pix);
    const float4 vy4 = make_float4(vy, vy, vy, vy);
    oy[0] = vy4;
    oy[1] = vy4;
}
} // namespace

extern "C" void kernel_launch(void* const* d_in, const int* in_sizes, int n_in,
                              void* d_out, int out_size)
{
    const float* gt    = (const float*)d_in[0];
    const float* theta = (const float*)d_in[1];
    float* out = (float*)d_out;

    dim3 grid(WO / 128, HO / 16, NB);   // (16, 64, 8)
    stn_kernel<<<grid, 256>>>(gt, theta, out);
}

// round 9
// speedup vs baseline: 1.0504x; 1.0504x over previous
#include <cuda_runtime.h>
#include <cuda_bf16.h>

// STN_fixTheta: fused 8x nearest-upsample + dual bilinear grid_sample.
// gt: [8,1,128,256] f32, theta: [8,6] f32.
// out: box [8,1,1024,2048] f32 followed by boxy [8,1,1024,2048] f32.
//
// Block-level smem staging: each 128x16-px block maps to a small gt bbox
// (affine); load it once into padded smem, gathers become LDS. Fallback to
// the proven global-load paths for OOB/edge/oversized-footprint blocks.

namespace {
constexpr int NB  = 8;
constexpr int HIN = 128;
constexpr int WIN = 256;
constexpr int HO  = 1024;
constexpr int WO  = 2048;
constexpr int PX  = 8;       // pixels per thread
constexpr int TW  = 64;      // smem tile max width  (texels)
constexpr int TH  = 32;      // smem tile max height (rows)
constexpr int TS  = TW + 1;  // padded stride (65: rotates banks)

// floor via 2^23 bias: no F2I/I2F cvt-pipe ops. Valid for |x| < ~4e6.
__device__ __forceinline__ void ffloor(float x, float& f, int& i) {
    const float MAGIC = 12582912.0f;            // 1.5 * 2^23
    float tt = x + MAGIC;
    float r  = tt - MAGIC;
    int   ri = __float_as_int(tt) - 0x4B400000;
    if (r > x) { r -= 1.0f; ri -= 1; }
    f = r; i = ri;
}

__global__ __launch_bounds__(256) void stn_kernel(
    const float* __restrict__ gt,
    const float* __restrict__ theta,
    float* __restrict__ out)
{
    __shared__ float tile[TH * TS];

    const int tid  = threadIdx.x;
    const int w    = tid >> 5;
    const int lane = tid & 31;
    const int lx   = lane & 7;           // 8 lanes in x
    const int ly   = lane >> 3;          // 4 rows in y
    const int wx   = w & 1;
    const int wy   = w >> 1;

    const int xo0 = blockIdx.x * 128 + wx * 64 + lx * 8;
    const int yo  = blockIdx.y * 16  + wy * 4  + ly;
    const int b   = blockIdx.z;

    const float2 th01 = __ldg(reinterpret_cast<const float2*>(theta + b * 6 + 0));
    const float2 th23 = __ldg(reinterpret_cast<const float2*>(theta + b * 6 + 2));
    const float2 th45 = __ldg(reinterpret_cast<const float2*>(theta + b * 6 + 4));
    const float t0 = th01.x, t1 = th01.y, t2 = th23.x, t3 = th23.y;
    const float t4 = th45.x, t5 = th45.y;

    const float ys = (yo + 0.5f) * (2.0f / HO) - 1.0f;
    const float* __restrict__ g = gt + b * (HIN * WIN);

    // ---------------- boxy: one value per thread (global loads) -------------
    const float gyy  = fmaf(t4, ys, t5);
    const float iyy  = (fmaf(gyy, (float)HO, (float)HO) - 1.0f) * 0.5f;
    float iy0f; int iy0y;
    ffloor(iyy, iy0f, iy0y);
    const float wyy  = iyy - iy0f;
    const bool  ok0  = (unsigned)iy0y < (unsigned)HO;
    const bool  ok1  = (unsigned)(iy0y + 1) < (unsigned)HO;
    float vy = 0.0f;
    if (ok0 | ok1) {
        const int   xc  = xo0 >> 3;
        const int   ry0 = (min(max(iy0y, 0), HO - 1)) >> 3;
        const int   ry1 = (min(max(iy0y + 1, 0), HO - 1)) >> 3;
        const float wA  = ok0 ? (1.0f - wyy) : 0.0f;
        const float wB  = ok1 ? wyy : 0.0f;
        vy = wA * g[ry0 * WIN + xc] + wB * g[ry1 * WIN + xc];
    }

    // ---------------- per-lane coordinate base ----------------
    const float xs0 = (xo0 + 0.5f) * (2.0f / WO) - 1.0f;
    const float gx0 = fmaf(t0, xs0, fmaf(t1, ys, t2));
    const float gy0 = fmaf(t3, xs0, fmaf(t4, ys, t5));
    const float ixb = (fmaf(gx0, (float)WO, (float)WO) - 1.0f) * 0.5f;
    const float iyb = (fmaf(gy0, (float)HO, (float)HO) - 1.0f) * 0.5f;
    const float sx  = t0;           // d ix / d xo (pixel)
    const float sy  = t3 * 0.5f;    // d iy / d xo

    // ---------------- block-uniform bbox / eligibility ----------------
    // block-origin pixel coords
    const float bxs = (blockIdx.x * 128 + 0.5f) * (2.0f / WO) - 1.0f;
    const float bys = (blockIdx.y * 16  + 0.5f) * (2.0f / HO) - 1.0f;
    const float c0x = (fmaf(fmaf(t0, bxs, fmaf(t1, bys, t2)), (float)WO, (float)WO) - 1.0f) * 0.5f;
    const float c0y = (fmaf(fmaf(t3, bxs, fmaf(t4, bys, t5)), (float)HO, (float)HO) - 1.0f) * 0.5f;
    const float rx  = 2.0f * t1;    // d ix / d yo (row)
    const float ry  = t4;           // d iy / d yo
    const float dxx = 127.0f * sx, dyx = 15.0f * rx;
    const float dxy = 127.0f * sy, dyy = 15.0f * ry;
    const float bixmin = c0x + fminf(dxx, 0.0f) + fminf(dyx, 0.0f);
    const float bixmax = c0x + fmaxf(dxx, 0.0f) + fmaxf(dyx, 0.0f);
    const float biymin = c0y + fminf(dxy, 0.0f) + fminf(dyy, 0.0f);
    const float biymax = c0y + fmaxf(dxy, 0.0f) + fmaxf(dyy, 0.0f);

    bool smem_ok = (bixmin >= 0.5f) && (bixmax <= (float)WO - 2.5f) &&
                   (biymin >= 0.5f) && (biymax <= (float)HO - 2.5f);

    int gxlo = 0, gylo = 0;
    if (smem_ok) {
        const int fxmin = (int)floorf(bixmin), fxmax = (int)floorf(bixmax);
        const int fymin = (int)floorf(biymin), fymax = (int)floorf(biymax);
        gxlo = max(0, fxmin - 1) >> 3;
        gylo = max(0, fymin - 1) >> 3;
        const int gxhi = min(WIN - 1, (fxmax + 2) >> 3);
        const int gyhi = min(HIN - 1, (fymax + 2) >> 3);
        const int Wt = gxhi - gxlo + 1;
        const int Ht = gyhi - gylo + 1;
        if (Wt <= TW && Ht <= TH) {
            // cooperative load: 4 rows x 64 cols per pass
            const int c  = tid & 63;
            const int r0 = tid >> 6;
            for (int r = r0; r < Ht; r += 4)
                if (c < Wt) tile[r * TS + c] = g[(gylo + r) * WIN + gxlo + c];
            __syncthreads();
        } else {
            smem_ok = false;
        }
    }

    float v[PX];

    if (smem_ok) {
        // all gathers from smem, no bounds checks, 4-px chunks
        #pragma unroll
        for (int cch = 0; cch < 2; ++cch) {
            int   o00[4], o10[4], o01[4], o11[4];
            float fwx[4], fwy[4];
            #pragma unroll
            for (int k = 0; k < 4; ++k) {
                const int   j  = cch * 4 + k;
                const float ix = fmaf((float)j, sx, ixb);
                const float iy = fmaf((float)j, sy, iyb);
                float fx, fy; int ix0, iy0;
                ffloor(ix, fx, ix0);
                ffloor(iy, fy, iy0);
                fwx[k] = ix - fx;
                fwy[k] = iy - fy;
                const int x0 = (ix0 >> 3) - gxlo;
                const int x1 = ((ix0 + 1) >> 3) - gxlo;
                const int y0 = (iy0 >> 3) - gylo;
                const int y1 = ((iy0 + 1) >> 3) - gylo;
                o00[k] = y0 * TS + x0;
                o10[k] = y0 * TS + x1;
                o01[k] = y1 * TS + x0;
                o11[k] = y1 * TS + x1;
            }
            float l00[4], l10[4], l01[4], l11[4];
            #pragma unroll
            for (int k = 0; k < 4; ++k) {
                l00[k] = tile[o00[k]];
                l10[k] = tile[o10[k]];
                l01[k] = tile[o01[k]];
                l11[k] = tile[o11[k]];
            }
            #pragma unroll
            for (int k = 0; k < 4; ++k) {
                const float a  = fmaf(fwx[k], l10[k] - l00[k], l00[k]);
                const float cc = fmaf(fwx[k], l11[k] - l01[k], l01[k]);
                v[cch * 4 + k] = fmaf(fwy[k], cc - a, a);
            }
        }
    } else {
        // -------- fallback: per-thread classified global paths (R5) --------
        const float ix7 = fmaf(7.0f, sx, ixb);
        const float iy7 = fmaf(7.0f, sy, iyb);
        const float ixmin = fminf(ixb, ix7), ixmax = fmaxf(ixb, ix7);
        const float iymin = fminf(iyb, iy7), iymax = fmaxf(iyb, iy7);

        if (ixmax < -1.0f || ixmin >= (float)WO || iymax < -1.0f || iymin >= (float)HO) {
            #pragma unroll
            for (int j = 0; j < PX; ++j) v[j] = 0.0f;
        } else if (ixmin >= 0.0f && ixmax < (float)(WO - 1) &&
                   iymin >= 0.0f && iymax < (float)(HO - 1)) {
            #pragma unroll
            for (int cch = 0; cch < 2; ++cch) {
                int   o00[4], o10[4], o01[4], o11[4];
                float fwx[4], fwy[4];
                #pragma unroll
                for (int k = 0; k < 4; ++k) {
                    const int   j  = cch * 4 + k;
                    const float ix = fmaf((float)j, sx, ixb);
                    const float iy = fmaf((float)j, sy, iyb);
                    float fx, fy; int ix0, iy0;
                    ffloor(ix, fx, ix0);
                    ffloor(iy, fy, iy0);
                    fwx[k] = ix - fx;
                    fwy[k] = iy - fy;
                    const int x0 = ix0 >> 3;
                    const int x1 = (ix0 + 1) >> 3;
                    const int y0 = iy0 >> 3;
                    const int y1 = (iy0 + 1) >> 3;
                    o00[k] = (y0 << 8) + x0;
                    o10[k] = (y0 << 8) + x1;
                    o01[k] = (y1 << 8) + x0;
                    o11[k] = (y1 << 8) + x1;
                }
                float l00[4], l10[4], l01[4], l11[4];
                #pragma unroll
                for (int k = 0; k < 4; ++k) {
                    l00[k] = g[o00[k]];
                    l10[k] = g[o10[k]];
                    l01[k] = g[o01[k]];
                    l11[k] = g[o11[k]];
                }
                #pragma unroll
                for (int k = 0; k < 4; ++k) {
                    const float a  = fmaf(fwx[k], l10[k] - l00[k], l00[k]);
                    const float cc = fmaf(fwx[k], l11[k] - l01[k], l01[k]);
                    v[cch * 4 + k] = fmaf(fwy[k], cc - a, a);
                }
            }
        } else {
            #pragma unroll
            for (int j = 0; j < PX; ++j) {
                const float ix = fmaf((float)j, sx, ixb);
                const float iy = fmaf((float)j, sy, iyb);
                float fx, fy; int ix0, iy0;
                ffloor(ix, fx, ix0);
                ffloor(iy, fy, iy0);
                const float wx_ = ix - fx;
                const float wy_ = iy - fy;
                const bool xv0 = (unsigned)ix0       < (unsigned)WO;
                const bool xv1 = (unsigned)(ix0 + 1) < (unsigned)WO;
                const bool yv0 = (unsigned)iy0       < (unsigned)HO;
                const bool yv1 = (unsigned)(iy0 + 1) < (unsigned)HO;
                const int x0 = (min(max(ix0, 0), WO - 1)) >> 3;
                const int x1 = (min(max(ix0 + 1, 0), WO - 1)) >> 3;
                const int y0 = (min(max(iy0, 0), HO - 1)) >> 3;
                const int y1 = (min(max(iy0 + 1, 0), HO - 1)) >> 3;
                const float w00 = (xv0 && yv0) ? (1.0f - wx_) * (1.0f - wy_) : 0.0f;
                const float w10 = (xv1 && yv0) ? wx_ * (1.0f - wy_) : 0.0f;
                const float w01 = (xv0 && yv1) ? (1.0f - wx_) * wy_ : 0.0f;
                const float w11 = (xv1 && yv1) ? wx_ * wy_ : 0.0f;
                v[j] = w00 * g[(y0 << 8) + x0]
                     + w10 * g[(y0 << 8) + x1]
                     + w01 * g[(y1 << 8) + x0]
                     + w11 * g[(y1 << 8) + x1];
            }
        }
    }

    const long long pix = ((long long)b * HO + yo) * WO + xo0;
    float4* ob = reinterpret_cast<float4*>(out + pix);
    ob[0] = make_float4(v[0], v[1], v[2], v[3]);
    ob[1] = make_float4(v[4], v[5], v[6], v[7]);
    float4* oy = reinterpret_cast<float4*>(out + (long long)NB * HO * WO + pix);
    const float4 vy4 = make_float4(vy, vy, vy, vy);
    oy[0] = vy4;
    oy[1] = vy4;
}
} // namespace

extern "C" void kernel_launch(void* const* d_in, const int* in_sizes, int n_in,
                              void* d_out, int out_size)
{
    const float* gt    = (const float*)d_in[0];
    const float* theta = (const float*)d_in[1];
    float* out = (float*)d_out;

    dim3 grid(WO / 128, HO / 16, NB);   // (16, 64, 8)
    stn_kernel<<<grid, 256>>>(gt, theta, out);
}

// round 10
// speedup vs baseline: 1.1967x; 1.1393x over previous
#include <cuda_runtime.h>
#include <cuda_bf16.h>

// STN_fixTheta: fused 8x nearest-upsample + dual bilinear grid_sample.
// gt: [8,1,128,256] f32, theta: [8,6] f32.
// out: box [8,1,1024,2048] f32 followed by boxy [8,1,1024,2048] f32.
//
// Fast path: a thread's 8 pixels span <=3x3 gt texels (8x upsample shrinks the
// footprint). Load that 3x3 once; per-pixel value is a saturate-weighted
// separable blend (exact: transitions only at texel boundaries, Sterbenz-exact
// weights). No per-pixel loads, no floors. Generic paths kept as fallback.

namespace {
constexpr int NB  = 8;
constexpr int HIN = 128;
constexpr int WIN = 256;
constexpr int HO  = 1024;
constexpr int WO  = 2048;
constexpr int PX  = 8;

// floor via 2^23 bias (fallback paths only)
__device__ __forceinline__ void ffloor(float x, float& f, int& i) {
    const float MAGIC = 12582912.0f;            // 1.5 * 2^23
    float tt = x + MAGIC;
    float r  = tt - MAGIC;
    int   ri = __float_as_int(tt) - 0x4B400000;
    if (r > x) { r -= 1.0f; ri -= 1; }
    f = r; i = ri;
}

__global__ __launch_bounds__(256, 6) void stn_kernel(
    const float* __restrict__ gt,
    const float* __restrict__ theta,
    float* __restrict__ out)
{
    const int tid  = threadIdx.x;
    const int w    = tid >> 5;
    const int lane = tid & 31;
    const int lx   = lane & 7;           // 8 lanes in x
    const int ly   = lane >> 3;          // 4 rows in y
    const int wx   = w & 1;
    const int wy   = w >> 1;

    const int xo0 = blockIdx.x * 128 + wx * 64 + lx * 8;
    const int yo  = blockIdx.y * 16  + wy * 4  + ly;
    const int b   = blockIdx.z;

    const float2 th01 = __ldg(reinterpret_cast<const float2*>(theta + b * 6 + 0));
    const float2 th23 = __ldg(reinterpret_cast<const float2*>(theta + b * 6 + 2));
    const float2 th45 = __ldg(reinterpret_cast<const float2*>(theta + b * 6 + 4));
    const float t0 = th01.x, t1 = th01.y, t2 = th23.x, t3 = th23.y;
    const float t4 = th45.x, t5 = th45.y;

    const float ys = (yo + 0.5f) * (2.0f / HO) - 1.0f;
    const float* __restrict__ g = gt + b * (HIN * WIN);

    // ---------------- boxy: one value per thread ----------------
    const float gyy  = fmaf(t4, ys, t5);
    const float iyy  = (fmaf(gyy, (float)HO, (float)HO) - 1.0f) * 0.5f;
    float iy0f; int iy0y;
    ffloor(iyy, iy0f, iy0y);
    const float wyy  = iyy - iy0f;
    const bool  ok0  = (unsigned)iy0y < (unsigned)HO;
    const bool  ok1  = (unsigned)(iy0y + 1) < (unsigned)HO;
    float vy = 0.0f;
    if (ok0 | ok1) {
        const int   xc  = xo0 >> 3;
        const int   ry0 = (min(max(iy0y, 0), HO - 1)) >> 3;
        const int   ry1 = (min(max(iy0y + 1, 0), HO - 1)) >> 3;
        const float wA  = ok0 ? (1.0f - wyy) : 0.0f;
        const float wB  = ok1 ? wyy : 0.0f;
        vy = wA * g[ry0 * WIN + xc] + wB * g[ry1 * WIN + xc];
    }

    // ---------------- box coordinate base ----------------
    const float xs0 = (xo0 + 0.5f) * (2.0f / WO) - 1.0f;
    const float gx0 = fmaf(t0, xs0, fmaf(t1, ys, t2));
    const float gy0 = fmaf(t3, xs0, fmaf(t4, ys, t5));
    const float ixb = (fmaf(gx0, (float)WO, (float)WO) - 1.0f) * 0.5f;
    const float iyb = (fmaf(gy0, (float)HO, (float)HO) - 1.0f) * 0.5f;
    const float sx  = t0;           // d ix / d xo
    const float sy  = t3 * 0.5f;    // d iy / d xo

    const float ix7 = fmaf(7.0f, sx, ixb);
    const float iy7 = fmaf(7.0f, sy, iyb);
    const float ixmin = fminf(ixb, ix7), ixmax = fmaxf(ixb, ix7);
    const float iymin = fminf(iyb, iy7), iymax = fmaxf(iyb, iy7);

    float v[PX];

    const bool interior = (ixmin >= 0.0f) && (ixmax < (float)(WO - 1)) &&
                          (iymin >= 0.0f) && (iymax < (float)(HO - 1));

    if (ixmax < -1.0f || ixmin >= (float)WO || iymax < -1.0f || iymin >= (float)HO) {
        #pragma unroll
        for (int j = 0; j < PX; ++j) v[j] = 0.0f;
    } else if (interior) {
        // texel bounding box of all corners (coords positive -> trunc == floor)
        const int xlo = ((int)ixmin) >> 3;
        const int xhi = (((int)ixmax) + 1) >> 3;
        const int ylo = ((int)iymin) >> 3;
        const int yhi = (((int)iymax) + 1) >> 3;

        if ((xhi - xlo) <= 2 && (yhi - ylo) <= 2) {
            // -------- register 3x3 fast path: 9 loads, zero per-pixel loads ----
            const int x1i = min(xlo + 1, WIN - 1);
            const int x2i = min(xlo + 2, WIN - 1);
            const int y1i = min(ylo + 1, HIN - 1);
            const int y2i = min(ylo + 2, HIN - 1);
            const float* r0 = g + ylo * WIN;
            const float* r1 = g + y1i * WIN;
            const float* r2 = g + y2i * WIN;
            const float a00 = r0[xlo], a01 = r0[x1i], a02 = r0[x2i];
            const float a10 = r1[xlo], a11 = r1[x1i], a12 = r1[x2i];
            const float a20 = r2[xlo], a21 = r2[x1i], a22 = r2[x2i];
            const float d00 = a01 - a00, d01 = a02 - a01;
            const float d10 = a11 - a10, d11 = a12 - a11;
            const float d20 = a21 - a20, d21 = a22 - a21;
            const float cx1 = (float)(8 * xlo + 7), cx2 = cx1 + 8.0f;
            const float cy1 = (float)(8 * ylo + 7), cy2 = cy1 + 8.0f;
            #pragma unroll
            for (int j = 0; j < PX; ++j) {
                const float ix  = fmaf((float)j, sx, ixb);
                const float iy  = fmaf((float)j, sy, iyb);
                const float Wx1 = __saturatef(ix - cx1);
                const float Wx2 = __saturatef(ix - cx2);
                const float Wy1 = __saturatef(iy - cy1);
                const float Wy2 = __saturatef(iy - cy2);
                const float u0 = fmaf(Wx2, d01, fmaf(Wx1, d00, a00));
                const float u1 = fmaf(Wx2, d11, fmaf(Wx1, d10, a10));
                const float u2 = fmaf(Wx2, d21, fmaf(Wx1, d20, a20));
                const float vv = fmaf(Wy1, u1 - u0, u0);
                v[j] = fmaf(Wy2, u2 - u1, vv);
            }
        } else {
            // -------- generic interior (batched global loads) --------
            #pragma unroll
            for (int cch = 0; cch < 2; ++cch) {
                int   o00[4], o10[4], o01[4], o11[4];
                float fwx[4], fwy[4];
                #pragma unroll
                for (int k = 0; k < 4; ++k) {
                    const int   j  = cch * 4 + k;
                    const float ix = fmaf((float)j, sx, ixb);
                    const float iy = fmaf((float)j, sy, iyb);
                    float fx, fy; int ix0, iy0;
                    ffloor(ix, fx, ix0);
                    ffloor(iy, fy, iy0);
                    fwx[k] = ix - fx;
                    fwy[k] = iy - fy;
                    const int x0 = ix0 >> 3;
                    const int x1 = (ix0 + 1) >> 3;
                    const int y0 = iy0 >> 3;
                    const int y1 = (iy0 + 1) >> 3;
                    o00[k] = (y0 << 8) + x0;
                    o10[k] = (y0 << 8) + x1;
                    o01[k] = (y1 << 8) + x0;
                    o11[k] = (y1 << 8) + x1;
                }
                float l00[4], l10[4], l01[4], l11[4];
                #pragma unroll
                for (int k = 0; k < 4; ++k) {
                    l00[k] = g[o00[k]];
                    l10[k] = g[o10[k]];
                    l01[k] = g[o01[k]];
                    l11[k] = g[o11[k]];
                }
                #pragma unroll
                for (int k = 0; k < 4; ++k) {
                    const float a  = fmaf(fwx[k], l10[k] - l00[k], l00[k]);
                    const float cc = fmaf(fwx[k], l11[k] - l01[k], l01[k]);
                    v[cch * 4 + k] = fmaf(fwy[k], cc - a, a);
                }
            }
        }
    } else {
        // -------- edge/mixed: general predicated path (rare) --------
        #pragma unroll
        for (int j = 0; j < PX; ++j) {
            const float ix = fmaf((float)j, sx, ixb);
            const float iy = fmaf((float)j, sy, iyb);
            float fx, fy; int ix0, iy0;
            ffloor(ix, fx, ix0);
            ffloor(iy, fy, iy0);
            const float wx_ = ix - fx;
            const float wy_ = iy - fy;
            const bool xv0 = (unsigned)ix0       < (unsigned)WO;
            const bool xv1 = (unsigned)(ix0 + 1) < (unsigned)WO;
            const bool yv0 = (unsigned)iy0       < (unsigned)HO;
            const bool yv1 = (unsigned)(iy0 + 1) < (unsigned)HO;
            const int x0 = (min(max(ix0, 0), WO - 1)) >> 3;
            const int x1 = (min(max(ix0 + 1, 0), WO - 1)) >> 3;
            const int y0 = (min(max(iy0, 0), HO - 1)) >> 3;
            const int y1 = (min(max(iy0 + 1, 0), HO - 1)) >> 3;
            const float w00 = (xv0 && yv0) ? (1.0f - wx_) * (1.0f - wy_) : 0.0f;
            const float w10 = (xv1 && yv0) ? wx_ * (1.0f - wy_) : 0.0f;
            const float w01 = (xv0 && yv1) ? (1.0f - wx_) * wy_ : 0.0f;
            const float w11 = (xv1 && yv1) ? wx_ * wy_ : 0.0f;
            v[j] = w00 * g[(y0 << 8) + x0]
                 + w10 * g[(y0 << 8) + x1]
                 + w01 * g[(y1 << 8) + x0]
                 + w11 * g[(y1 << 8) + x1];
        }
    }

    const long long pix = ((long long)b * HO + yo) * WO + xo0;
    float4* ob = reinterpret_cast<float4*>(out + pix);
    ob[0] = make_float4(v[0], v[1], v[2], v[3]);
    ob[1] = make_float4(v[4], v[5], v[6], v[7]);
    float4* oy = reinterpret_cast<float4*>(out + (long long)NB * HO * WO + pix);
    const float4 vy4 = make_float4(vy, vy, vy, vy);
    oy[0] = vy4;
    oy[1] = vy4;
}
} // namespace

extern "C" void kernel_launch(void* const* d_in, const int* in_sizes, int n_in,
                              void* d_out, int out_size)
{
    const float* gt    = (const float*)d_in[0];
    const float* theta = (const float*)d_in[1];
    float* out = (float*)d_out;

    dim3 grid(WO / 128, HO / 16, NB);   // (16, 64, 8)
    stn_kernel<<<grid, 256>>>(gt, theta, out);
}

// round 11
// speedup vs baseline: 1.2141x; 1.0146x over previous
#include <cuda_runtime.h>
#include <cuda_bf16.h>

// STN_fixTheta: fused 8x nearest-upsample + dual bilinear grid_sample.
// gt: [8,1,128,256] f32, theta: [8,6] f32.
// out: box [8,1,1024,2048] f32 followed by boxy [8,1,1024,2048] f32.
//
// Fast path: a thread's 8 pixels span <=3x3 gt texels (8x upsample shrinks
// the footprint). Load the 3x3 once; per-pixel value is a saturate-weighted
// separable blend (exact at fp32: transitions only at texel boundaries).
// Tuned for 8 CTAs/SM (32 regs): boxy stored early, box stored in 4-px halves.

namespace {
constexpr int NB  = 8;
constexpr int HIN = 128;
constexpr int WIN = 256;
constexpr int HO  = 1024;
constexpr int WO  = 2048;
constexpr int PX  = 8;

// floor via 2^23 bias (fallback paths only)
__device__ __forceinline__ void ffloor(float x, float& f, int& i) {
    const float MAGIC = 12582912.0f;            // 1.5 * 2^23
    float tt = x + MAGIC;
    float r  = tt - MAGIC;
    int   ri = __float_as_int(tt) - 0x4B400000;
    if (r > x) { r -= 1.0f; ri -= 1; }
    f = r; i = ri;
}

__global__ __launch_bounds__(256, 8) void stn_kernel(
    const float* __restrict__ gt,
    const float* __restrict__ theta,
    float* __restrict__ out)
{
    const int tid  = threadIdx.x;
    const int w    = tid >> 5;
    const int lane = tid & 31;
    const int lx   = lane & 7;           // 8 lanes in x
    const int ly   = lane >> 3;          // 4 rows in y
    const int wx   = w & 1;
    const int wy   = w >> 1;

    const int xo0 = blockIdx.x * 128 + wx * 64 + lx * 8;
    const int yo  = blockIdx.y * 16  + wy * 4  + ly;
    const int b   = blockIdx.z;

    const float2 th01 = __ldg(reinterpret_cast<const float2*>(theta + b * 6 + 0));
    const float2 th23 = __ldg(reinterpret_cast<const float2*>(theta + b * 6 + 2));
    const float2 th45 = __ldg(reinterpret_cast<const float2*>(theta + b * 6 + 4));
    const float t0 = th01.x, t1 = th01.y, t2 = th23.x, t3 = th23.y;
    const float t4 = th45.x, t5 = th45.y;

    const float ys = (yo + 0.5f) * (2.0f / HO) - 1.0f;
    const float* __restrict__ g = gt + b * (HIN * WIN);
    const long long pix = ((long long)b * HO + yo) * WO + xo0;

    // ---------------- boxy: compute AND store immediately ----------------
    {
        const float gyy  = fmaf(t4, ys, t5);
        const float iyy  = (fmaf(gyy, (float)HO, (float)HO) - 1.0f) * 0.5f;
        float iy0f; int iy0y;
        ffloor(iyy, iy0f, iy0y);
        const float wyy  = iyy - iy0f;
        const bool  ok0  = (unsigned)iy0y < (unsigned)HO;
        const bool  ok1  = (unsigned)(iy0y + 1) < (unsigned)HO;
        float vy = 0.0f;
        if (ok0 | ok1) {
            const int   xc  = xo0 >> 3;
            const int   ry0 = (min(max(iy0y, 0), HO - 1)) >> 3;
            const int   ry1 = (min(max(iy0y + 1, 0), HO - 1)) >> 3;
            const float wA  = ok0 ? (1.0f - wyy) : 0.0f;
            const float wB  = ok1 ? wyy : 0.0f;
            vy = wA * g[ry0 * WIN + xc] + wB * g[ry1 * WIN + xc];
        }
        float4* oy = reinterpret_cast<float4*>(out + (long long)NB * HO * WO + pix);
        const float4 vy4 = make_float4(vy, vy, vy, vy);
        oy[0] = vy4;
        oy[1] = vy4;
    }

    // ---------------- box coordinate base ----------------
    const float xs0 = (xo0 + 0.5f) * (2.0f / WO) - 1.0f;
    const float gx0 = fmaf(t0, xs0, fmaf(t1, ys, t2));
    const float gy0 = fmaf(t3, xs0, fmaf(t4, ys, t5));
    const float ixb = (fmaf(gx0, (float)WO, (float)WO) - 1.0f) * 0.5f;
    const float iyb = (fmaf(gy0, (float)HO, (float)HO) - 1.0f) * 0.5f;
    const float sx  = t0;           // d ix / d xo
    const float sy  = t3 * 0.5f;    // d iy / d xo

    const float ix7 = fmaf(7.0f, sx, ixb);
    const float iy7 = fmaf(7.0f, sy, iyb);
    const float ixmin = fminf(ixb, ix7), ixmax = fmaxf(ixb, ix7);
    const float iymin = fminf(iyb, iy7), iymax = fmaxf(iyb, iy7);

    float4* ob = reinterpret_cast<float4*>(out + pix);

    const bool interior = (ixmin >= 0.0f) && (ixmax < (float)(WO - 1)) &&
                          (iymin >= 0.0f) && (iymax < (float)(HO - 1));

    if (ixmax < -1.0f || ixmin >= (float)WO || iymax < -1.0f || iymin >= (float)HO) {
        const float4 z = make_float4(0.0f, 0.0f, 0.0f, 0.0f);
        ob[0] = z;
        ob[1] = z;
        return;
    }

    if (interior) {
        const int xlo = ((int)ixmin) >> 3;
        const int xhi = (((int)ixmax) + 1) >> 3;
        const int ylo = ((int)iymin) >> 3;
        const int yhi = (((int)iymax) + 1) >> 3;

        if ((xhi - xlo) <= 2 && (yhi - ylo) <= 2) {
            // -------- register 3x3 fast path --------
            const int x1i = min(xlo + 1, WIN - 1);
            const int x2i = min(xlo + 2, WIN - 1);
            const int y1i = min(ylo + 1, HIN - 1);
            const int y2i = min(ylo + 2, HIN - 1);
            const float* r0 = g + ylo * WIN;
            const float* r1 = g + y1i * WIN;
            const float* r2 = g + y2i * WIN;
            const float a00 = r0[xlo], a01 = r0[x1i], a02 = r0[x2i];
            const float a10 = r1[xlo], a11 = r1[x1i], a12 = r1[x2i];
            const float a20 = r2[xlo], a21 = r2[x1i], a22 = r2[x2i];
            const float d00 = a01 - a00, d01 = a02 - a01;
            const float d10 = a11 - a10, d11 = a12 - a11;
            const float d20 = a21 - a20, d21 = a22 - a21;
            const float cx1 = (float)(8 * xlo + 7), cx2 = cx1 + 8.0f;
            const float cy1 = (float)(8 * ylo + 7), cy2 = cy1 + 8.0f;
            #pragma unroll
            for (int h = 0; h < 2; ++h) {
                float v[4];
                #pragma unroll
                for (int k = 0; k < 4; ++k) {
                    const int   j   = h * 4 + k;
                    const float ix  = fmaf((float)j, sx, ixb);
                    const float iy  = fmaf((float)j, sy, iyb);
                    const float Wx1 = __saturatef(ix - cx1);
                    const float Wx2 = __saturatef(ix - cx2);
                    const float Wy1 = __saturatef(iy - cy1);
                    const float Wy2 = __saturatef(iy - cy2);
                    const float u0 = fmaf(Wx2, d01, fmaf(Wx1, d00, a00));
                    const float u1 = fmaf(Wx2, d11, fmaf(Wx1, d10, a10));
                    const float u2 = fmaf(Wx2, d21, fmaf(Wx1, d20, a20));
                    const float vv = fmaf(Wy1, u1 - u0, u0);
                    v[k] = fmaf(Wy2, u2 - u1, vv);
                }
                ob[h] = make_float4(v[0], v[1], v[2], v[3]);
            }
        } else {
            // -------- generic interior (batched global loads), 4-px halves ----
            #pragma unroll
            for (int h = 0; h < 2; ++h) {
                int   o00[4], o10[4], o01[4], o11[4];
                float fwx[4], fwy[4];
                #pragma unroll
                for (int k = 0; k < 4; ++k) {
                    const int   j  = h * 4 + k;
                    const float ix = fmaf((float)j, sx, ixb);
                    const float iy = fmaf((float)j, sy, iyb);
                    float fx, fy; int ix0, iy0;
                    ffloor(ix, fx, ix0);
                    ffloor(iy, fy, iy0);
                    fwx[k] = ix - fx;
                    fwy[k] = iy - fy;
                    const int x0 = ix0 >> 3;
                    const int x1 = (ix0 + 1) >> 3;
                    const int y0 = iy0 >> 3;
                    const int y1 = (iy0 + 1) >> 3;
                    o00[k] = (y0 << 8) + x0;
                    o10[k] = (y0 << 8) + x1;
                    o01[k] = (y1 << 8) + x0;
                    o11[k] = (y1 << 8) + x1;
                }
                float l00[4], l10[4], l01[4], l11[4];
                #pragma unroll
                for (int k = 0; k < 4; ++k) {
                    l00[k] = g[o00[k]];
                    l10[k] = g[o10[k]];
                    l01[k] = g[o01[k]];
                    l11[k] = g[o11[k]];
                }
                float v[4];
                #pragma unroll
                for (int k = 0; k < 4; ++k) {
                    const float a  = fmaf(fwx[k], l10[k] - l00[k], l00[k]);
                    const float cc = fmaf(fwx[k], l11[k] - l01[k], l01[k]);
                    v[k] = fmaf(fwy[k], cc - a, a);
                }
                ob[h] = make_float4(v[0], v[1], v[2], v[3]);
            }
        }
    } else {
        // -------- edge/mixed: general predicated path (rare) --------
        #pragma unroll
        for (int h = 0; h < 2; ++h) {
            float v[4];
            #pragma unroll
            for (int k = 0; k < 4; ++k) {
                const int   j  = h * 4 + k;
                const float ix = fmaf((float)j, sx, ixb);
                const float iy = fmaf((float)j, sy, iyb);
                float fx, fy; int ix0, iy0;
                ffloor(ix, fx, ix0);
                ffloor(iy, fy, iy0);
                const float wx_ = ix - fx;
                const float wy_ = iy - fy;
                const bool xv0 = (unsigned)ix0       < (unsigned)WO;
                const bool xv1 = (unsigned)(ix0 + 1) < (unsigned)WO;
                const bool yv0 = (unsigned)iy0       < (unsigned)HO;
                const bool yv1 = (unsigned)(iy0 + 1) < (unsigned)HO;
                const int x0 = (min(max(ix0, 0), WO - 1)) >> 3;
                const int x1 = (min(max(ix0 + 1, 0), WO - 1)) >> 3;
                const int y0 = (min(max(iy0, 0), HO - 1)) >> 3;
                const int y1 = (min(max(iy0 + 1, 0), HO - 1)) >> 3;
                const float w00 = (xv0 && yv0) ? (1.0f - wx_) * (1.0f - wy_) : 0.0f;
                const float w10 = (xv1 && yv0) ? wx_ * (1.0f - wy_) : 0.0f;
                const float w01 = (xv0 && yv1) ? (1.0f - wx_) * wy_ : 0.0f;
                const float w11 = (xv1 && yv1) ? wx_ * wy_ : 0.0f;
                v[k] = w00 * g[(y0 << 8) + x0]
                     + w10 * g[(y0 << 8) + x1]
                     + w01 * g[(y1 << 8) + x0]
                     + w11 * g[(y1 << 8) + x1];
            }
            ob[h] = make_float4(v[0], v[1], v[2], v[3]);
        }
    }
}
} // namespace

extern "C" void kernel_launch(void* const* d_in, const int* in_sizes, int n_in,
                              void* d_out, int out_size)
{
    const float* gt    = (const float*)d_in[0];
    const float* theta = (const float*)d_in[1];
    float* out = (float*)d_out;

    dim3 grid(WO / 128, HO / 16, NB);   // (16, 64, 8)
    stn_kernel<<<grid, 256>>>(gt, theta, out);
}